// round 5
// baseline (speedup 1.0000x reference)
#include <cuda_runtime.h>
#include <math.h>
#include <stdint.h>

#define SEQ   512
#define BATCH 64
#define INDIM 128
#define HDIM  512
#define CLUSTER_G 8
#define BT        4
#define JC        64
#define NTHREADS  512
#define NWARPS    16
#define KWH       32            // Wh k-range per warp (16 warps)
#define KWI2      16            // Wi k-range per worker warp (warps 8..15)

// SMEM byte offsets
#define OFF_BIAS   0                               // float[64]
#define OFF_HRAW   256                             // float[2][512][4]   = 16384
#define OFF_XDUP   (OFF_HRAW + 16384)              // float2[2][128][4]  = 8192
#define OFF_PART   (OFF_XDUP + 8192)               // float[16][64][4]   = 16384
#define OFF_PARTWI (OFF_PART + 16384)              // float[2][8][4][64] = 16384
#define OFF_WIT    (OFF_PARTWI + 16384)            // float[128][64]     = 32768
#define OFF_STAGE  (OFF_WIT + 32768)               // float[64][4]       = 1024
#define OFF_BARS   (OFF_STAGE + 1024)              // 4 x u64
#define OFF_WTMP   (OFF_BARS + 64)                 // float[64][512] init staging
#define SMEM_BYTES (OFF_WTMP + JC*HDIM*4)          // 222,528 B

__device__ __forceinline__ void cluster_sync_all() {
    asm volatile("barrier.cluster.arrive.aligned;" ::: "memory");
    asm volatile("barrier.cluster.wait.aligned;" ::: "memory");
}
__device__ __forceinline__ uint32_t smem_u32(const void* p) {
    return (uint32_t)__cvta_generic_to_shared(p);
}
__device__ __forceinline__ void mbar_init(uint32_t a, uint32_t cnt) {
    asm volatile("mbarrier.init.shared.b64 [%0], %1;" :: "r"(a), "r"(cnt) : "memory");
}
__device__ __forceinline__ void mbar_arrive_expect_tx(uint32_t a, uint32_t tx) {
    asm volatile("mbarrier.arrive.expect_tx.shared.b64 _, [%0], %1;" :: "r"(a), "r"(tx) : "memory");
}
__device__ __forceinline__ void mbar_remote_arrive(uint32_t a, uint32_t rank) {
    asm volatile(
        "{\n\t.reg .b32 ra;\n\t"
        "mapa.shared::cluster.u32 ra, %0, %1;\n\t"
        "mbarrier.arrive.shared::cluster.b64 _, [ra];\n\t}"
        :: "r"(a), "r"(rank) : "memory");
}
__device__ __forceinline__ void mbar_wait_parity(uint32_t a, uint32_t ph) {
    asm volatile(
        "{\n\t.reg .pred P;\n"
        "W_%=:\n\t"
        "mbarrier.try_wait.parity.acquire.cta.shared::cta.b64 P, [%0], %1, 0x989680;\n\t"
        "@P bra D_%=;\n\t"
        "bra W_%=;\n"
        "D_%=:\n\t}"
        :: "r"(a), "r"(ph) : "memory");
}
__device__ __forceinline__ void bulk_copy_to_peer(uint32_t dst_local, uint32_t src,
                                                  uint32_t bytes, uint32_t mbar_local,
                                                  uint32_t rank) {
    asm volatile(
        "{\n\t.reg .b32 rd, rb;\n\t"
        "mapa.shared::cluster.u32 rd, %0, %4;\n\t"
        "mapa.shared::cluster.u32 rb, %3, %4;\n\t"
        "cp.async.bulk.shared::cluster.shared::cta.mbarrier::complete_tx::bytes [rd], [%1], %2, [rb];\n\t}"
        :: "r"(dst_local), "r"(src), "r"(bytes), "r"(mbar_local), "r"(rank) : "memory");
}
__device__ __forceinline__ long long fma2(long long a, long long b, long long c) {
    long long d;
    asm("fma.rn.f32x2 %0, %1, %2, %3;" : "=l"(d) : "l"(a), "l"(b), "l"(c));
    return d;
}
__device__ __forceinline__ long long dup2(float x) {
    long long d;
    asm("mov.b64 %0, {%1, %1};" : "=l"(d) : "f"(x));
    return d;
}

// Wi(t') partial GEMM for worker warps 8..15 (hidden behind reduce/exchange).
// j-pair accumulators, weights pre-packed in WiT[k][j], x duplicated in xdup.
__device__ __forceinline__ void wi_partial(const float* WiT, const float2* xd,
                                           float* part_wi, int buf, int r, int j2) {
    long long c0 = 0, c1 = 0, c2 = 0, c3 = 0;   // batches 0..3, (j2,j2+1) pairs
    const float2* xc = xd + buf * (INDIM * BT);
    const int kb = r * KWI2;
    #pragma unroll
    for (int kk = 0; kk < KWI2; kk++) {
        const int k = kb + kk;
        const long long w = *reinterpret_cast<const long long*>(WiT + k * JC + j2);
        const longlong2 q01 = *reinterpret_cast<const longlong2*>(xc + k * BT);
        const longlong2 q23 = *reinterpret_cast<const longlong2*>(xc + k * BT + 2);
        c0 = fma2(q01.x, w, c0); c1 = fma2(q01.y, w, c1);
        c2 = fma2(q23.x, w, c2); c3 = fma2(q23.y, w, c3);
    }
    float* pw = part_wi + buf * (8 * BT * JC) + r * (BT * JC);
    *reinterpret_cast<long long*>(pw + 0 * JC + j2) = c0;
    *reinterpret_cast<long long*>(pw + 1 * JC + j2) = c1;
    *reinterpret_cast<long long*>(pw + 2 * JC + j2) = c2;
    *reinterpret_cast<long long*>(pw + 3 * JC + j2) = c3;
}

__global__ void __cluster_dims__(CLUSTER_G, 1, 1) __launch_bounds__(NTHREADS, 1)
rnn_persistent_kernel(const float* __restrict__ x,
                      const float* __restrict__ Wi,
                      const float* __restrict__ bi,
                      const float* __restrict__ Wh,
                      const float* __restrict__ bh,
                      float* __restrict__ out)
{
    extern __shared__ char smem[];
    float*  bias    = (float*)(smem + OFF_BIAS);
    float*  hraw    = (float*)(smem + OFF_HRAW);    // [buf][k][b]
    float2* xdup    = (float2*)(smem + OFF_XDUP);   // [buf][k][b] entries (v,v)
    float*  part    = (float*)(smem + OFF_PART);    // [w][jl][b]
    float*  part_wi = (float*)(smem + OFF_PARTWI);  // [buf][r][b][jl]
    float*  WiT     = (float*)(smem + OFF_WIT);     // [k][j] packed
    float*  stage   = (float*)(smem + OFF_STAGE);   // [jl][b]
    float*  Wtmp    = (float*)(smem + OFF_WTMP);

    const int tid  = threadIdx.x;
    const int rank = blockIdx.x & (CLUSTER_G - 1);
    const int cl   = blockIdx.x >> 3;
    const int b0   = cl * BT;
    const int j0   = rank * JC;

    const uint32_t hraw_base  = smem_u32(hraw);
    const uint32_t stage_base = smem_u32(stage);
    const uint32_t full_bar0  = smem_u32(smem + OFF_BARS);
    const uint32_t empty_bar0 = full_bar0 + 16;

    const int warp = tid >> 5;
    const int lane = tid & 31;
    const int j2   = lane << 1;

    // ---- init
    if (tid < JC) bias[tid] = bi[j0 + tid] + bh[j0 + tid];
    for (int i = tid; i < HDIM * BT; i += NTHREADS) hraw[i] = 0.0f;
    {   // xdup[0] <- x(0), xdup[1] <- x(1)
        int k = tid >> 2, b = tid & 3;
        float v0 = x[(size_t)(b0 + b) * INDIM + k];
        float v1 = x[(size_t)BATCH * INDIM + (size_t)(b0 + b) * INDIM + k];
        xdup[tid] = make_float2(v0, v0);
        xdup[INDIM * BT + tid] = make_float2(v1, v1);
    }
    for (int i = tid; i < INDIM * JC; i += NTHREADS) {   // WiT[k][j]
        int k = i >> 6, j = i & (JC - 1);
        WiT[i] = Wi[(size_t)(j0 + j) * INDIM + k];
    }
    if (tid == 0) {
        mbar_init(full_bar0 + 0, 1);
        mbar_init(full_bar0 + 8, 1);
        mbar_init(empty_bar0 + 0, 8);
        mbar_init(empty_bar0 + 8, 8);
        mbar_arrive_expect_tx(full_bar0 + 0, 8192);
        mbar_arrive_expect_tx(full_bar0 + 8, 8192);
    }

    // ---- stage Wh shard -> per-thread register weights
    __syncthreads();
    for (int i = tid; i < JC * HDIM; i += NTHREADS)
        Wtmp[i] = Wh[(size_t)j0 * HDIM + i];               // [jl][k]
    __syncthreads();
    float wha[KWH], whb[KWH];
    {
        const int kb = warp * KWH;
        #pragma unroll
        for (int kk = 0; kk < KWH; kk++) {
            wha[kk] = Wtmp[j2 * HDIM + kb + kk];
            whb[kk] = Wtmp[(j2 + 1) * HDIM + kb + kk];
        }
    }
    __syncthreads();

    // prologue: Wi(0) partials into part_wi[0] (worker warps)
    if (warp >= 8) wi_partial(WiT, xdup, part_wi, 0, warp - 8, j2);
    __syncthreads();

    cluster_sync_all();
    if (tid == 0) {    // pre-release empty[1]
        #pragma unroll
        for (int p = 0; p < CLUSTER_G; p++) mbar_remote_arrive(empty_bar0 + 8, (uint32_t)p);
    }

    for (int t = 0; t < SEQ; t++) {
        const int cur = t & 1;
        const int nxt = cur ^ 1;

        // ---- wait for h(t)
        if (t > 0) {
            mbar_wait_parity(full_bar0 + cur * 8, (uint32_t)(((t - 1) >> 1) & 1));
            if (tid == 0) mbar_arrive_expect_tx(full_bar0 + cur * 8, 8192);
        }

        // ---- Phase A: Wh GEMM, all 16 warps (b-pair acc, register weights)
        {
            long long a0 = 0, a1 = 0, a2 = 0, a3 = 0;
            const float* hc = hraw + cur * (HDIM * BT) + (warp * KWH) * BT;
            #pragma unroll
            for (int kk = 0; kk < KWH; kk++) {
                const longlong2 p = *reinterpret_cast<const longlong2*>(hc + (kk << 2));
                const long long wa = dup2(wha[kk]);
                const long long wb = dup2(whb[kk]);
                a0 = fma2(p.x, wa, a0); a1 = fma2(p.y, wa, a1);
                a2 = fma2(p.x, wb, a2); a3 = fma2(p.y, wb, a3);
            }
            float* pp = part + warp * (BT * JC) + (j2 << 2);
            *reinterpret_cast<ulonglong2*>(pp + 0) =
                make_ulonglong2((unsigned long long)a0, (unsigned long long)a1);
            *reinterpret_cast<ulonglong2*>(pp + 4) =
                make_ulonglong2((unsigned long long)a2, (unsigned long long)a3);
        }

        __syncthreads();   // partials visible; hraw[cur] fully consumed

        if (warp == 1 && lane < CLUSTER_G)   // release hraw[cur] to all peers
            mbar_remote_arrive(empty_bar0 + cur * 8, (uint32_t)lane);

        if (warp < 8) {
            // ---- reduce 16 Wh rows + 8 Wi rows, tanh, out, stage
            const int jl = (tid & 255) >> 2;     // tid<256 mapping
            const int b  = tid & 3;
            if (tid < BT * JC) {
                float s = 0.0f;
                #pragma unroll
                for (int w = 0; w < NWARPS; w++)
                    s += part[w * (BT * JC) + tid];
                const float* pw = part_wi + cur * (8 * BT * JC) + b * JC + jl;
                #pragma unroll
                for (int r = 0; r < 8; r++)
                    s += pw[r * (BT * JC)];
                const float v = tanhf(s + bias[jl]);

                out[(size_t)t * BATCH * HDIM + (b0 + b) * HDIM + (j0 + jl)] = v;
                if (t == SEQ - 1)
                    out[(size_t)SEQ * BATCH * HDIM + (b0 + b) * HDIM + (j0 + jl)] = v;
                stage[tid] = v;
            }
            asm volatile("bar.sync 1, 256;" ::: "memory");   // warps 0-7

            if (t + 1 < SEQ && warp == 0 && lane < CLUSTER_G) {
                asm volatile("fence.proxy.async.shared::cta;" ::: "memory");
                mbar_wait_parity(empty_bar0 + nxt * 8, (uint32_t)((t >> 1) & 1));
                const uint32_t dst = hraw_base + (uint32_t)((nxt * HDIM * BT + j0 * BT) * 4);
                bulk_copy_to_peer(dst, stage_base, (uint32_t)(JC * BT * 4),
                                  full_bar0 + nxt * 8, (uint32_t)lane);
            }
        } else {
            // ---- hidden work: Wi(t+1) + prefetch x(t+2)
            if (t + 1 < SEQ)
                wi_partial(WiT, xdup, part_wi, nxt, warp - 8, j2);
            if (t + 2 < SEQ) {
                const int idx = (warp - 8) * 32 + lane;       // 0..255, two entries each
                #pragma unroll
                for (int h = 0; h < 2; h++) {
                    const int i  = idx + h * 256;
                    const int pk = i >> 2, pb = i & 3;
                    const float v = x[(size_t)(t + 2) * BATCH * INDIM +
                                      (size_t)(b0 + pb) * INDIM + pk];
                    xdup[cur * (INDIM * BT) + i] = make_float2(v, v);
                }
            }
        }
    }

    cluster_sync_all();
}

extern "C" void kernel_launch(void* const* d_in, const int* in_sizes, int n_in,
                              void* d_out, int out_size) {
    const float* x  = (const float*)d_in[0];
    const float* Wi = (const float*)d_in[1];
    const float* bi = (const float*)d_in[2];
    const float* Wh = (const float*)d_in[3];
    const float* bh = (const float*)d_in[4];
    float* out = (float*)d_out;

    cudaFuncSetAttribute(rnn_persistent_kernel,
                         cudaFuncAttributeMaxDynamicSharedMemorySize, SMEM_BYTES);

    rnn_persistent_kernel<<<(BATCH / BT) * CLUSTER_G, NTHREADS, SMEM_BYTES>>>(
        x, Wi, bi, Wh, bh, out);
}

// round 6
// speedup vs baseline: 1.2596x; 1.2596x over previous
#include <cuda_runtime.h>
#include <math.h>
#include <stdint.h>

#define SEQ   512
#define BATCH 64
#define INDIM 128
#define HDIM  512
#define CLUSTER_G 8
#define BT        4
#define JC        64
#define NTHREADS  512
#define NWARPS    16
#define KWH       32
#define KWI       8

// SMEM byte offsets
#define OFF_BIAS   0                               // float[64]
#define OFF_HRAW   256                             // float[2][512][4] = 16384
#define OFF_XRAW   (OFF_HRAW + 16384)              // float[2][128][4] = 4096
#define OFF_PART   (OFF_XRAW + 4096)               // float[16][64][4] = 16384
#define OFF_STAGE  (OFF_PART + 16384)              // float[2][64][4]  = 2048
#define OFF_BARS   (OFF_STAGE + 2048)              // 16 full + 2 empty mbarriers
#define OFF_WTMP   (OFF_BARS + 192)                // float[64][512] init staging
#define SMEM_BYTES (OFF_WTMP + JC*HDIM*4)          // ~170,560 B

__device__ __forceinline__ void cluster_sync_all() {
    asm volatile("barrier.cluster.arrive.aligned;" ::: "memory");
    asm volatile("barrier.cluster.wait.aligned;" ::: "memory");
}
__device__ __forceinline__ uint32_t smem_u32(const void* p) {
    return (uint32_t)__cvta_generic_to_shared(p);
}
__device__ __forceinline__ void mbar_init(uint32_t a, uint32_t cnt) {
    asm volatile("mbarrier.init.shared.b64 [%0], %1;" :: "r"(a), "r"(cnt) : "memory");
}
__device__ __forceinline__ void mbar_arrive_expect_tx(uint32_t a, uint32_t tx) {
    asm volatile("mbarrier.arrive.expect_tx.shared.b64 _, [%0], %1;" :: "r"(a), "r"(tx) : "memory");
}
__device__ __forceinline__ void mbar_remote_arrive(uint32_t a, uint32_t rank) {
    asm volatile(
        "{\n\t.reg .b32 ra;\n\t"
        "mapa.shared::cluster.u32 ra, %0, %1;\n\t"
        "mbarrier.arrive.shared::cluster.b64 _, [ra];\n\t}"
        :: "r"(a), "r"(rank) : "memory");
}
__device__ __forceinline__ void mbar_wait_parity(uint32_t a, uint32_t ph) {
    asm volatile(
        "{\n\t.reg .pred P;\n"
        "W_%=:\n\t"
        "mbarrier.try_wait.parity.acquire.cta.shared::cta.b64 P, [%0], %1, 0x989680;\n\t"
        "@P bra D_%=;\n\t"
        "bra W_%=;\n"
        "D_%=:\n\t}"
        :: "r"(a), "r"(ph) : "memory");
}
__device__ __forceinline__ void bulk_copy_to_peer(uint32_t dst_local, uint32_t src,
                                                  uint32_t bytes, uint32_t mbar_local,
                                                  uint32_t rank) {
    asm volatile(
        "{\n\t.reg .b32 rd, rb;\n\t"
        "mapa.shared::cluster.u32 rd, %0, %4;\n\t"
        "mapa.shared::cluster.u32 rb, %3, %4;\n\t"
        "cp.async.bulk.shared::cluster.shared::cta.mbarrier::complete_tx::bytes [rd], [%1], %2, [rb];\n\t}"
        :: "r"(dst_local), "r"(src), "r"(bytes), "r"(mbar_local), "r"(rank) : "memory");
}
__device__ __forceinline__ long long fma2(long long a, long long b, long long c) {
    long long d;
    asm("fma.rn.f32x2 %0, %1, %2, %3;" : "=l"(d) : "l"(a), "l"(b), "l"(c));
    return d;
}
__device__ __forceinline__ long long dup2(float x) {
    long long d;
    asm("mov.b64 %0, {%1, %1};" : "=l"(d) : "f"(x));
    return d;
}
__device__ __forceinline__ float tanh_fast(float x) {
    float y;
    asm("tanh.approx.f32 %0, %1;" : "=f"(y) : "f"(x));
    return y;
}

__global__ void __cluster_dims__(CLUSTER_G, 1, 1) __launch_bounds__(NTHREADS, 1)
rnn_persistent_kernel(const float* __restrict__ x,
                      const float* __restrict__ Wi,
                      const float* __restrict__ bi,
                      const float* __restrict__ Wh,
                      const float* __restrict__ bh,
                      float* __restrict__ out)
{
    extern __shared__ char smem[];
    float* bias  = (float*)(smem + OFF_BIAS);
    float* hraw  = (float*)(smem + OFF_HRAW);    // [buf][k][b]
    float* xraw  = (float*)(smem + OFF_XRAW);    // [buf][k][b]
    float* part  = (float*)(smem + OFF_PART);    // [w][jl][b]
    float* stage = (float*)(smem + OFF_STAGE);   // [buf][jl][b]
    float* Wtmp  = (float*)(smem + OFF_WTMP);

    const int tid  = threadIdx.x;
    const int rank = blockIdx.x & (CLUSTER_G - 1);
    const int cl   = blockIdx.x >> 3;
    const int b0   = cl * BT;
    const int j0   = rank * JC;

    const uint32_t hraw_base  = smem_u32(hraw);
    const uint32_t stage_base = smem_u32(stage);
    const uint32_t bars_base  = smem_u32(smem + OFF_BARS);
    // full[buf][q] at bars_base + (buf*8+q)*8 ; empty[buf] at bars_base + 128 + buf*8
    #define FULL_BAR(buf,q) (bars_base + (uint32_t)(((buf) * 8 + (q)) * 8))
    #define EMPTY_BAR(buf)  (bars_base + 128u + (uint32_t)((buf) * 8))

    const int warp = tid >> 5;
    const int lane = tid & 31;
    const int j2   = lane << 1;
    const int myq  = warp >> 1;     // peer whose h-slice this warp consumes

    // ---- init
    if (tid < JC) bias[tid] = bi[j0 + tid] + bh[j0 + tid];
    for (int i = tid; i < HDIM * BT; i += NTHREADS) hraw[i] = 0.0f;
    {   // x(0) prefetch, warp-local mapping: entry i = warp*32+lane
        const int i  = tid;
        const int pk = i >> 2, pb = i & 3;
        xraw[i] = x[(size_t)(b0 + pb) * INDIM + pk];
    }
    if (tid == 0) {
        #pragma unroll
        for (int q = 0; q < 16; q++) {
            mbar_init(bars_base + q * 8, 1);
            mbar_arrive_expect_tx(bars_base + q * 8, 1024);   // arm phase 0
        }
        mbar_init(EMPTY_BAR(0), 16);
        mbar_init(EMPTY_BAR(1), 16);
    }

    // ---- Wh shard -> registers
    __syncthreads();
    for (int i = tid; i < JC * HDIM; i += NTHREADS)
        Wtmp[i] = Wh[(size_t)j0 * HDIM + i];
    __syncthreads();
    float wha[KWH], whb[KWH];
    {
        const int kb = warp * KWH;
        #pragma unroll
        for (int kk = 0; kk < KWH; kk++) {
            wha[kk] = Wtmp[j2 * HDIM + kb + kk];
            whb[kk] = Wtmp[(j2 + 1) * HDIM + kb + kk];
        }
    }
    __syncthreads();
    for (int i = tid; i < JC * INDIM; i += NTHREADS)
        Wtmp[i] = Wi[(size_t)j0 * INDIM + i];
    __syncthreads();
    float wia[KWI], wib[KWI];
    {
        const int kb = warp * KWI;
        #pragma unroll
        for (int kk = 0; kk < KWI; kk++) {
            wia[kk] = Wtmp[j2 * INDIM + kb + kk];
            wib[kk] = Wtmp[(j2 + 1) * INDIM + kb + kk];
        }
    }
    __syncthreads();

    cluster_sync_all();          // barriers + h0/x0 visible cluster-wide
    if (tid < 16)                // pre-release empty[1]: 2 arrivals to each peer
        mbar_remote_arrive(EMPTY_BAR(1), (uint32_t)(tid >> 1));

    for (int t = 0; t < SEQ; t++) {
        const int cur = t & 1;
        const int nxt = cur ^ 1;

        // prefetch x(t+1): warp-local entries only (i = warp*32+lane)
        float xv = 0.0f;
        if (t + 1 < SEQ)
            xv = x[(size_t)(t + 1) * BATCH * INDIM +
                   (size_t)(b0 + (tid & 3)) * INDIM + (tid >> 2)];

        long long a0 = 0, a1 = 0, a2 = 0, a3 = 0;

        // ---- Wi segment (independent of h exchange)
        {
            const float* xc = xraw + cur * (INDIM * BT) + (warp * KWI) * BT;
            #pragma unroll
            for (int kk = 0; kk < KWI; kk++) {
                const longlong2 p = *reinterpret_cast<const longlong2*>(xc + (kk << 2));
                const long long wa = dup2(wia[kk]);
                const long long wb = dup2(wib[kk]);
                a0 = fma2(p.x, wa, a0); a1 = fma2(p.y, wa, a1);
                a2 = fma2(p.x, wb, a2); a3 = fma2(p.y, wb, a3);
            }
        }

        // ---- wait for OUR peer's h-slice only, then re-arm (even warp of pair)
        if (t > 0) {
            mbar_wait_parity(FULL_BAR(cur, myq), (uint32_t)(((t - 1) >> 1) & 1));
            if ((warp & 1) == 0 && lane == 0)
                mbar_arrive_expect_tx(FULL_BAR(cur, myq), 1024);
        }

        // ---- Wh chunk (register weights, b-pair accumulators)
        {
            const float* hc = hraw + cur * (HDIM * BT) + (warp * KWH) * BT;
            #pragma unroll
            for (int kk = 0; kk < KWH; kk++) {
                const longlong2 p = *reinterpret_cast<const longlong2*>(hc + (kk << 2));
                const long long wa = dup2(wha[kk]);
                const long long wb = dup2(whb[kk]);
                a0 = fma2(p.x, wa, a0); a1 = fma2(p.y, wa, a1);
                a2 = fma2(p.x, wb, a2); a3 = fma2(p.y, wb, a3);
            }
        }

        // partials
        {
            float* pp = part + warp * (BT * JC) + (j2 << 2);
            *reinterpret_cast<ulonglong2*>(pp + 0) =
                make_ulonglong2((unsigned long long)a0, (unsigned long long)a1);
            *reinterpret_cast<ulonglong2*>(pp + 4) =
                make_ulonglong2((unsigned long long)a2, (unsigned long long)a3);
        }

        // notify writer CTA myq: its slot in OUR hraw[cur] is consumed
        if (lane == 0) mbar_remote_arrive(EMPTY_BAR(cur), (uint32_t)myq);

        // store prefetched x (warp-local entries; read only by this warp next step)
        xraw[nxt * (INDIM * BT) + tid] = xv;

        // ---- split barrier: producers arrive, reduce warps sync
        if (warp >= 8) {
            asm volatile("bar.arrive 0, %0;" :: "n"(NTHREADS) : "memory");
            continue;   // straight to next step's Wi + per-peer wait
        }
        asm volatile("bar.sync 0, %0;" :: "n"(NTHREADS) : "memory");

        // ---- reduce + tanh + stage + out  (warps 0..7, tid<256)
        {
            const int jl = tid >> 2;
            const int b  = tid & 3;
            float s = bias[jl];
            #pragma unroll
            for (int w = 0; w < NWARPS; w++)
                s += part[w * (BT * JC) + tid];
            const float v = tanh_fast(s);

            stage[cur * (BT * JC) + tid] = v;
            out[(size_t)t * BATCH * HDIM + (b0 + b) * HDIM + (j0 + jl)] = v;
            if (t == SEQ - 1)
                out[(size_t)SEQ * BATCH * HDIM + (b0 + b) * HDIM + (j0 + jl)] = v;
        }
        asm volatile("bar.sync 1, 256;" ::: "memory");

        // ---- exchange: 8 parallel 1KB copies, per-peer full barriers
        if (t + 1 < SEQ && warp == 0) {
            if (lane == 0)
                mbar_wait_parity(EMPTY_BAR(nxt), (uint32_t)((t >> 1) & 1));
            __syncwarp();
            if (lane < CLUSTER_G) {
                asm volatile("fence.proxy.async.shared::cta;" ::: "memory");
                const uint32_t dst = hraw_base + (uint32_t)((nxt * HDIM * BT + j0 * BT) * 4);
                bulk_copy_to_peer(dst, stage_base + (uint32_t)(cur * BT * JC * 4),
                                  (uint32_t)(JC * BT * 4),
                                  FULL_BAR(nxt, rank), (uint32_t)lane);
            }
        }
    }

    cluster_sync_all();
}

extern "C" void kernel_launch(void* const* d_in, const int* in_sizes, int n_in,
                              void* d_out, int out_size) {
    const float* x  = (const float*)d_in[0];
    const float* Wi = (const float*)d_in[1];
    const float* bi = (const float*)d_in[2];
    const float* Wh = (const float*)d_in[3];
    const float* bh = (const float*)d_in[4];
    float* out = (float*)d_out;

    cudaFuncSetAttribute(rnn_persistent_kernel,
                         cudaFuncAttributeMaxDynamicSharedMemorySize, SMEM_BYTES);

    rnn_persistent_kernel<<<(BATCH / BT) * CLUSTER_G, NTHREADS, SMEM_BYTES>>>(
        x, Wi, bi, Wh, bh, out);
}